// round 15
// baseline (speedup 1.0000x reference)
#include <cuda_runtime.h>
#include <cuda_bf16.h>
#include <cstdint>

// Problem constants (z: [32,64,64,64] f32, codebook: [1024,64] f32)
#define BB      32
#define CC      64
#define HWN     4096
#define NQ      (BB * HWN)        // 131072 queries
#define KCODES  1024
#define MTILE   128               // queries per CTA
#define NCHUNK  128               // codes staged per smem chunk
#define NCH     (KCODES / NCHUNK) // 8
#define THREADS 128
#define NBLOCKS (NQ / MTILE)      // 1024
#define ZELEMS  (BB * CC * HWN)
#define EPS_SCREEN 0.75f          // screen window (2x bf16 err 0.25 + pack 0.008 + margin)
#define EPS_TIE    5e-3f          // fp32 diff-form tie gate (>>2e-5 error bound)
#define SBIAS      256.0f         // score bias: makes all screen scores positive
#define PADW    72                // row stride (bf16): 144B = 9*16B, ldmatrix conflict-free

#define BBYTES  (NCHUNK * PADW * 2)            // 18432 per chunk image
#define OFF_BUF0   0
#define OFF_BUF1   (BBYTES + 512)              // 18944
#define OFF_SCN0   BBYTES
#define OFF_SCN1   (OFF_BUF1 + BBYTES)
#define OFF_WERR   (OFF_BUF1 + BBYTES + 512)   // 37888
#define SMEM_TOTAL (OFF_WERR + 64)             // 37952

__device__ float g_cnorm[KCODES];              // ||c||^2 + SBIAS
__device__ float g_partials[NBLOCKS];
__device__ unsigned int g_ctr = 0;
// prepped codebook: bf16 of (-2c), rows padded to PADW
__device__ __align__(16) __nv_bfloat16 g_cbimg[KCODES * PADW];

// ---------------------------------------------------------------------------
__device__ __forceinline__ uint32_t smem_to_u32(const void* p) {
    uint32_t a;
    asm("{ .reg .u64 t; cvta.to.shared.u64 t, %1; cvt.u32.u64 %0, t; }"
        : "=r"(a) : "l"(p));
    return a;
}
__device__ __forceinline__ uint32_t umn(uint32_t a, uint32_t b) { return a < b ? a : b; }
__device__ __forceinline__ uint32_t umx(uint32_t a, uint32_t b) { return a > b ? a : b; }

#define LDSM_X4(r, addr) \
    asm volatile("ldmatrix.sync.aligned.m8n8.x4.shared.b16 {%0,%1,%2,%3}, [%4];" \
        : "=r"((r)[0]), "=r"((r)[1]), "=r"((r)[2]), "=r"((r)[3]) : "r"(addr))

// accumulate: d += a*b
#define MMA16816(d, a, b) \
    asm volatile("mma.sync.aligned.m16n8k16.row.col.f32.bf16.bf16.f32 " \
        "{%0,%1,%2,%3}, {%4,%5,%6,%7}, {%8,%9}, {%0,%1,%2,%3};" \
        : "+f"((d)[0]), "+f"((d)[1]), "+f"((d)[2]), "+f"((d)[3]) \
        : "r"((a)[0]), "r"((a)[1]), "r"((a)[2]), "r"((a)[3]), \
          "r"((b)[0]), "r"((b)[1]))

// init: d = a*b + {c0,c1,c0,c1}
#define MMA16816_INIT(d, a, b, c0, c1) \
    asm volatile("mma.sync.aligned.m16n8k16.row.col.f32.bf16.bf16.f32 " \
        "{%0,%1,%2,%3}, {%4,%5,%6,%7}, {%8,%9}, {%10,%11,%10,%11};" \
        : "=f"((d)[0]), "=f"((d)[1]), "=f"((d)[2]), "=f"((d)[3]) \
        : "r"((a)[0]), "r"((a)[1]), "r"((a)[2]), "r"((a)[3]), \
          "r"((b)[0]), "r"((b)[1]), "f"(c0), "f"(c1))

#define CP_ASYNC16(sm, gp) \
    asm volatile("cp.async.cg.shared.global [%0], [%1], 16;" :: "r"(sm), "l"(gp))
#define CP_ASYNC4(sm, gp) \
    asm volatile("cp.async.ca.shared.global [%0], [%1], 4;" :: "r"(sm), "l"(gp))
#define CP_COMMIT() asm volatile("cp.async.commit_group;" ::: "memory")
#define CP_WAIT1()  asm volatile("cp.async.wait_group 1;" ::: "memory")

// ---------------------------------------------------------------------------
// Kernel 0: prep — cn = ||c||^2 + SBIAS (fp32 exact), bf16 image of (-2c)
// ---------------------------------------------------------------------------
__global__ void prep_kernel(const float* __restrict__ cb) {
    int k = blockIdx.x * blockDim.x + threadIdx.x;
    if (k >= KCODES) return;
    const float2* r = reinterpret_cast<const float2*>(cb + (size_t)k * CC);
    __nv_bfloat16* row = g_cbimg + (size_t)k * PADW;
    float cn = 0.f;
#pragma unroll
    for (int c = 0; c < CC / 2; c++) {
        float2 v = __ldg(r + c);
        cn = fmaf(v.x, v.x, cn);
        cn = fmaf(v.y, v.y, cn);
        __nv_bfloat162 hp;
        hp.x = __float2bfloat16_rn(-2.f * v.x);
        hp.y = __float2bfloat16_rn(-2.f * v.y);
        *reinterpret_cast<__nv_bfloat162*>(row + 2 * c) = hp;
    }
    g_cnorm[k] = cn + SBIAS;
}

// fp64 exact squared distance (tier-2, rare)
__device__ double dist2_f64(const float* __restrict__ zp,
                            const float* __restrict__ cb, int idx) {
    const float* cp = cb + (size_t)idx * CC;
    double d = 0.0;
#pragma unroll
    for (int c = 0; c < CC; c++) {
        double df = (double)zp[(size_t)c * HWN] - (double)__ldg(cp + c);
        d = fma(df, df, d);
    }
    return d;
}

// ---------------------------------------------------------------------------
// Kernel 1: HMMA VQ — bf16 screen, packed branch-free top-4-of-256,
//           fp32 rescore + fp64 tie refinement, fused deterministic loss
// ---------------------------------------------------------------------------
extern __shared__ unsigned char dynsmem[];

__global__ __launch_bounds__(THREADS, 5)
void vq_kernel(const float* __restrict__ z,
               const float* __restrict__ cb,
               float* __restrict__ out,
               float* __restrict__ loss_out) {
    const int tid = threadIdx.x;
    const int w = tid >> 5;
    const int l = tid & 31;
    const uint32_t sb = smem_to_u32(dynsmem);

    __nv_bfloat16* Ahi = reinterpret_cast<__nv_bfloat16*>(dynsmem + OFF_BUF0);
    float* werr = reinterpret_cast<float*>(dynsmem + OFF_WERR);
    uint32_t* cand = reinterpret_cast<uint32_t*>(dynsmem + OFF_BUF0);  // post-loop

    const int q = blockIdx.x * MTILE + tid;
    const int b = q >> 12;
    const float* zp = z + (size_t)b * CC * HWN + (q & (HWN - 1));

    // --- A tile: z query -> bf16 hi, staged transiently in buf0.B ---
#pragma unroll
    for (int c = 0; c < CC; c++)
        Ahi[tid * PADW + c] = __float2bfloat16_rn(zp[(size_t)c * HWN]);
    __syncthreads();

    // --- hoist A fragments: 4 k-slices x (a0[4], a1[4]) = 32 regs ---
    const int rowA = w * 32 + (l & 15);
    const int colA = ((l >> 4) & 1) * 8;
    uint32_t afr[32];
#pragma unroll
    for (int fi = 0; fi < 4; fi++) {
        LDSM_X4(afr + fi * 8,
                sb + OFF_BUF0 + (uint32_t)((rowA)      * PADW + colA + fi * 16) * 2);
        LDSM_X4(afr + fi * 8 + 4,
                sb + OFF_BUF0 + (uint32_t)((rowA + 16) * PADW + colA + fi * 16) * 2);
    }
    __syncthreads();   // buf0 free for prefetch

    // --- prefetch chunks 0,1 via cp.async (double buffer) ---
    const uint32_t bufB[2]   = { sb + OFF_BUF0, sb + OFF_BUF1 };
    const uint32_t bufSCN[2] = { sb + OFF_SCN0, sb + OFF_SCN1 };
#pragma unroll
    for (int p = 0; p < 2; p++) {
        const char* src = reinterpret_cast<const char*>(g_cbimg) + (size_t)p * BBYTES;
#pragma unroll
        for (int i = 0; i < 9; i++)
            CP_ASYNC16(bufB[p] + (uint32_t)(tid + i * THREADS) * 16,
                       src + (size_t)(tid + i * THREADS) * 16);
        CP_ASYNC4(bufSCN[p] + (uint32_t)tid * 4,
                  reinterpret_cast<const char*>(g_cnorm) + (size_t)(p * NCHUNK + tid) * 4);
        CP_COMMIT();
    }

    // per-slot packed top-4 (sorted ascending). slot = mt*2 + (e>>1).
    // packed = (float_bits(score) & ~0xFF) | (iter*8 + nt*2 + e1)
    uint32_t pm[16];
#pragma unroll
    for (int i = 0; i < 16; i++) pm[i] = 0xFFFFFFFFu;

    const int rowB = ((l >> 4) & 1) * 8 + (l & 7);
    const int colB = ((l >> 3) & 1) * 8;

#pragma unroll 1
    for (int ch = 0; ch < NCH; ch++) {
        CP_WAIT1();
        __syncthreads();

        const uint32_t Bc = bufB[ch & 1];
        const float* scn = reinterpret_cast<const float*>(
            dynsmem + (((ch & 1) ? OFF_SCN1 : OFF_SCN0)));

#pragma unroll 1
        for (int nsub = 0; nsub < 4; nsub++) {
            float2 cnp[4];
#pragma unroll
            for (int nt = 0; nt < 4; nt++)
                cnp[nt] = *reinterpret_cast<const float2*>(
                    scn + nsub * 32 + nt * 8 + 2 * (l & 3));

            float d[32];
            const uint32_t bbase = Bc + (uint32_t)((nsub * 32 + rowB) * PADW + colB) * 2;

#pragma unroll
            for (int s = 0; s < 4; s++) {
                uint32_t bf[8];
                LDSM_X4(bf,     bbase + (uint32_t)(s * 16) * 2);
                LDSM_X4(bf + 4, bbase + (uint32_t)(16 * PADW + s * 16) * 2);
                const uint32_t* a0 = afr + s * 8;
                if (s == 0) {
#pragma unroll
                    for (int nt = 0; nt < 4; nt++) {
                        MMA16816_INIT(d + (0 * 4 + nt) * 4, a0,     bf + nt * 2,
                                      cnp[nt].x, cnp[nt].y);
                        MMA16816_INIT(d + (1 * 4 + nt) * 4, a0 + 4, bf + nt * 2,
                                      cnp[nt].x, cnp[nt].y);
                    }
                } else {
#pragma unroll
                    for (int nt = 0; nt < 4; nt++) {
                        MMA16816(d + (0 * 4 + nt) * 4, a0,     bf + nt * 2);
                        MMA16816(d + (1 * 4 + nt) * 4, a0 + 4, bf + nt * 2);
                    }
                }
            }

            // packed branch-free top-4 insert: 1 LOP3 + 7 IMNMX per score
            const uint32_t base8 = (uint32_t)((ch * 4 + nsub) * 8);
#pragma unroll
            for (int mt = 0; mt < 2; mt++)
#pragma unroll
                for (int nt = 0; nt < 4; nt++)
#pragma unroll
                    for (int e = 0; e < 4; e++) {
                        uint32_t x = (__float_as_uint(d[(mt * 4 + nt) * 4 + e])
                                      & 0xFFFFFF00u)
                                   | (base8 + (uint32_t)(nt * 2 + (e & 1)));
                        uint32_t* p = pm + (mt * 2 + (e >> 1)) * 4;
                        uint32_t t;
                        t = umn(p[0], x); x = umx(p[0], x); p[0] = t;
                        t = umn(p[1], x); x = umx(p[1], x); p[1] = t;
                        t = umn(p[2], x); x = umx(p[2], x); p[2] = t;
                        p[3] = umn(p[3], x);
                    }
        }

        __syncthreads();
        if (ch + 2 < NCH) {
            const char* src = reinterpret_cast<const char*>(g_cbimg) + (size_t)(ch + 2) * BBYTES;
#pragma unroll
            for (int i = 0; i < 9; i++)
                CP_ASYNC16(bufB[ch & 1] + (uint32_t)(tid + i * THREADS) * 16,
                           src + (size_t)(tid + i * THREADS) * 16);
            CP_ASYNC4(bufSCN[ch & 1] + (uint32_t)tid * 4,
                      reinterpret_cast<const char*>(g_cnorm) + (size_t)((ch + 2) * NCHUNK + tid) * 4);
            CP_COMMIT();
        }
    }

    // --- merge packed candidates via smem (stride 17; reuses buf0) ---
    // entry j of query: j>>2 = producing lane group (l&3), j&3 = rank
#pragma unroll
    for (int s = 0; s < 4; s++) {
        int mt = s >> 1, half = s & 1;
        int ql = w * 32 + mt * 16 + half * 8 + (l >> 2);
#pragma unroll
        for (int e = 0; e < 4; e++)
            cand[ql * 17 + (l & 3) * 4 + e] = pm[s * 4 + e];
    }
    __syncthreads();

    // --- per-query (thread = query): window + fp32 rescore + fp64 tie ---
    // pass 1: min over the 16 packed candidates (re-read smem; no reg cache)
    uint32_t pmin = cand[tid * 17];
#pragma unroll
    for (int j = 1; j < 16; j++) pmin = umn(pmin, cand[tid * 17 + j]);
    const float smin = __uint_as_float(pmin & 0xFFFFFF00u);

    // pass 2: decode window candidates
    int wc[16]; int nw = 0;
#pragma unroll
    for (int j = 0; j < 16; j++) {
        uint32_t pj = cand[tid * 17 + j];
        float sc = __uint_as_float(pj & 0xFFFFFF00u);
        if (sc < smin + EPS_SCREEN) {
            uint32_t low = pj & 0xFFu;
            wc[nw++] = (int)(low >> 3) * 32 + (int)((low >> 1) & 3) * 8
                     + 2 * (j >> 2) + (int)(low & 1);
        }
    }

    int bidx;
    if (nw == 1) {
        bidx = wc[0];
    } else {
        // tier 1: fp32 diff-form, two candidates per pass; track best/second
        float best = 3.4e38f, second = 3.4e38f;
        int   bi = 0x7fffffff;
#pragma unroll 1
        for (int j0 = 0; j0 < nw; j0 += 2) {
            int iA = wc[j0];
            int iB = wc[(j0 + 1 < nw) ? (j0 + 1) : j0];
            const float4* pA = reinterpret_cast<const float4*>(cb + (size_t)iA * CC);
            const float4* pB = reinterpret_cast<const float4*>(cb + (size_t)iB * CC);
            float dA0 = 0.f, dA1 = 0.f, dB0 = 0.f, dB1 = 0.f;
#pragma unroll
            for (int c = 0; c < CC / 4; c++) {
                float4 a4 = __ldg(pA + c);
                float4 b4 = __ldg(pB + c);
                float z0 = zp[(size_t)(4 * c + 0) * HWN];
                float z1 = zp[(size_t)(4 * c + 1) * HWN];
                float z2 = zp[(size_t)(4 * c + 2) * HWN];
                float z3 = zp[(size_t)(4 * c + 3) * HWN];
                float tA0 = z0 - a4.x, tA1 = z1 - a4.y, tA2 = z2 - a4.z, tA3 = z3 - a4.w;
                float tB0 = z0 - b4.x, tB1 = z1 - b4.y, tB2 = z2 - b4.z, tB3 = z3 - b4.w;
                dA0 = fmaf(tA0, tA0, dA0); dA1 = fmaf(tA1, tA1, dA1);
                dA0 = fmaf(tA2, tA2, dA0); dA1 = fmaf(tA3, tA3, dA1);
                dB0 = fmaf(tB0, tB0, dB0); dB1 = fmaf(tB1, tB1, dB1);
                dB0 = fmaf(tB2, tB2, dB0); dB1 = fmaf(tB3, tB3, dB1);
            }
            float dA = dA0 + dA1;
            float dB = dB0 + dB1;
            if (dA < best || (dA == best && iA < bi)) {
                second = best; best = dA; bi = iA;
            } else {
                second = fminf(second, dA);
            }
            if (j0 + 1 < nw) {
                if (dB < best || (dB == best && iB < bi)) {
                    second = best; best = dB; bi = iB;
                } else {
                    second = fminf(second, dB);
                }
            }
        }

        // tier 2: fp64 over the whole window, only on fp32 near-tie (rare)
        if (second < best + EPS_TIE) {
            double bd = 1e300;
            int bi64 = 0x7fffffff;
#pragma unroll 1
            for (int j = 0; j < nw; j++) {
                double dd = dist2_f64(zp, cb, wc[j]);
                if (dd < bd || (dd == bd && wc[j] < bi64)) { bd = dd; bi64 = wc[j]; }
            }
            bi = bi64;
        }
        bidx = bi;
    }

    // --- write z_q + squared-error partial (coalesced; cb row as float4) ---
    float err = 0.f;
    {
        const float4* cv4 = reinterpret_cast<const float4*>(cb + (size_t)bidx * CC);
        float* op = out + (size_t)b * CC * HWN + (q & (HWN - 1));
#pragma unroll
        for (int i = 0; i < CC / 4; i++) {
            float4 v = __ldg(cv4 + i);
            float z0 = zp[(size_t)(4 * i + 0) * HWN];
            float z1 = zp[(size_t)(4 * i + 1) * HWN];
            float z2 = zp[(size_t)(4 * i + 2) * HWN];
            float z3 = zp[(size_t)(4 * i + 3) * HWN];
            op[(size_t)(4 * i + 0) * HWN] = v.x;
            op[(size_t)(4 * i + 1) * HWN] = v.y;
            op[(size_t)(4 * i + 2) * HWN] = v.z;
            op[(size_t)(4 * i + 3) * HWN] = v.w;
            float d0 = v.x - z0, d1 = v.y - z1, d2 = v.z - z2, d3 = v.w - z3;
            err = fmaf(d0, d0, err);
            err = fmaf(d1, d1, err);
            err = fmaf(d2, d2, err);
            err = fmaf(d3, d3, err);
        }
    }
#pragma unroll
    for (int o = 16; o > 0; o >>= 1)
        err += __shfl_down_sync(0xFFFFFFFFu, err, o);
    if (l == 0) werr[w] = err;
    __syncthreads();

    // --- fused deterministic loss: last CTA reduces all partials ---
    __shared__ unsigned int s_last;
    if (tid == 0) {
        g_partials[blockIdx.x] = werr[0] + werr[1] + werr[2] + werr[3];
        __threadfence();
        unsigned int old = atomicAdd(&g_ctr, 1u);
        s_last = (old == NBLOCKS - 1) ? 1u : 0u;
    }
    __syncthreads();
    if (s_last) {
        __threadfence();  // acquire: all partials visible
        double* sd = reinterpret_cast<double*>(dynsmem);  // loop done; reuse smem
        double acc = 0.0;
#pragma unroll
        for (int i = 0; i < NBLOCKS / THREADS; i++)
            acc += (double)g_partials[tid * (NBLOCKS / THREADS) + i];
        sd[tid] = acc;
        __syncthreads();
#pragma unroll
        for (int st = THREADS / 2; st > 0; st >>= 1) {
            if (tid < st) sd[tid] += sd[tid + st];
            __syncthreads();
        }
        if (tid == 0) {
            if (loss_out)
                loss_out[0] = (float)(1.25 * sd[0] / (double)ZELEMS);
            g_ctr = 0;  // reset for next graph replay
        }
    }
}

// ---------------------------------------------------------------------------
extern "C" void kernel_launch(void* const* d_in, const int* in_sizes, int n_in,
                              void* d_out, int out_size) {
    const float* z  = (const float*)d_in[0];
    const float* cb = (const float*)d_in[1];
    float* out = (float*)d_out;
    float* loss_out = (out_size > ZELEMS) ? (out + ZELEMS) : nullptr;

    cudaFuncSetAttribute(vq_kernel, cudaFuncAttributeMaxDynamicSharedMemorySize,
                         SMEM_TOTAL);

    prep_kernel<<<8, 128>>>(cb);
    vq_kernel<<<NBLOCKS, THREADS, SMEM_TOTAL>>>(z, cb, out, loss_out);
}

// round 16
// speedup vs baseline: 1.0152x; 1.0152x over previous
#include <cuda_runtime.h>
#include <cuda_bf16.h>
#include <cstdint>

// Problem constants (z: [32,64,64,64] f32, codebook: [1024,64] f32)
#define BB      32
#define CC      64
#define HWN     4096
#define NQ      (BB * HWN)        // 131072 queries
#define KCODES  1024
#define MTILE   64                // queries per CTA (one m16 tile per warp)
#define NCHUNK  128               // codes staged per smem chunk
#define NCH     (KCODES / NCHUNK) // 8
#define THREADS 128
#define NBLOCKS (NQ / MTILE)      // 2048
#define ZELEMS  (BB * CC * HWN)
#define EPS_SCREEN 0.75f          // screen window (2x bf16 err + pack 0.008 + margin)
#define EPS_TIE    5e-3f          // fp32 diff-form tie gate (>>2e-5 error bound)
#define SBIAS      256.0f         // score bias: makes all screen scores positive
#define PADW    72                // row stride (bf16): 144B = 9*16B, ldmatrix conflict-free

#define BBYTES  (NCHUNK * PADW * 2)            // 18432 per chunk image
#define OFF_BUF0   0
#define OFF_BUF1   (BBYTES + 512)              // 18944
#define OFF_SCN0   BBYTES
#define OFF_SCN1   (OFF_BUF1 + BBYTES)
#define OFF_WERR   (OFF_BUF1 + BBYTES + 512)   // 37888
#define SMEM_TOTAL (OFF_WERR + 64)             // 37952

__device__ float g_cnorm[KCODES];              // ||c||^2 + SBIAS
__device__ float g_partials[NBLOCKS];
__device__ unsigned int g_ctr = 0;
// prepped codebook: bf16 of (-2c), rows padded to PADW
__device__ __align__(16) __nv_bfloat16 g_cbimg[KCODES * PADW];

// ---------------------------------------------------------------------------
__device__ __forceinline__ uint32_t smem_to_u32(const void* p) {
    uint32_t a;
    asm("{ .reg .u64 t; cvta.to.shared.u64 t, %1; cvt.u32.u64 %0, t; }"
        : "=r"(a) : "l"(p));
    return a;
}
__device__ __forceinline__ uint32_t umn(uint32_t a, uint32_t b) { return a < b ? a : b; }
__device__ __forceinline__ uint32_t umx(uint32_t a, uint32_t b) { return a > b ? a : b; }

#define LDSM_X4(r, addr) \
    asm volatile("ldmatrix.sync.aligned.m8n8.x4.shared.b16 {%0,%1,%2,%3}, [%4];" \
        : "=r"((r)[0]), "=r"((r)[1]), "=r"((r)[2]), "=r"((r)[3]) : "r"(addr))

// accumulate: d += a*b
#define MMA16816(d, a, b) \
    asm volatile("mma.sync.aligned.m16n8k16.row.col.f32.bf16.bf16.f32 " \
        "{%0,%1,%2,%3}, {%4,%5,%6,%7}, {%8,%9}, {%0,%1,%2,%3};" \
        : "+f"((d)[0]), "+f"((d)[1]), "+f"((d)[2]), "+f"((d)[3]) \
        : "r"((a)[0]), "r"((a)[1]), "r"((a)[2]), "r"((a)[3]), \
          "r"((b)[0]), "r"((b)[1]))

// init: d = a*b + {c0,c1,c0,c1}
#define MMA16816_INIT(d, a, b, c0, c1) \
    asm volatile("mma.sync.aligned.m16n8k16.row.col.f32.bf16.bf16.f32 " \
        "{%0,%1,%2,%3}, {%4,%5,%6,%7}, {%8,%9}, {%10,%11,%10,%11};" \
        : "=f"((d)[0]), "=f"((d)[1]), "=f"((d)[2]), "=f"((d)[3]) \
        : "r"((a)[0]), "r"((a)[1]), "r"((a)[2]), "r"((a)[3]), \
          "r"((b)[0]), "r"((b)[1]), "f"(c0), "f"(c1))

#define CP_ASYNC16(sm, gp) \
    asm volatile("cp.async.cg.shared.global [%0], [%1], 16;" :: "r"(sm), "l"(gp))
#define CP_ASYNC4(sm, gp) \
    asm volatile("cp.async.ca.shared.global [%0], [%1], 4;" :: "r"(sm), "l"(gp))
#define CP_COMMIT() asm volatile("cp.async.commit_group;" ::: "memory")
#define CP_WAIT1()  asm volatile("cp.async.wait_group 1;" ::: "memory")

// ---------------------------------------------------------------------------
// Kernel 0: prep — cn = ||c||^2 + SBIAS (fp32 exact), bf16 image of (-2c)
// ---------------------------------------------------------------------------
__global__ void prep_kernel(const float* __restrict__ cb) {
    int k = blockIdx.x * blockDim.x + threadIdx.x;
    if (k >= KCODES) return;
    const float2* r = reinterpret_cast<const float2*>(cb + (size_t)k * CC);
    __nv_bfloat16* row = g_cbimg + (size_t)k * PADW;
    float cn = 0.f;
#pragma unroll
    for (int c = 0; c < CC / 2; c++) {
        float2 v = __ldg(r + c);
        cn = fmaf(v.x, v.x, cn);
        cn = fmaf(v.y, v.y, cn);
        __nv_bfloat162 hp;
        hp.x = __float2bfloat16_rn(-2.f * v.x);
        hp.y = __float2bfloat16_rn(-2.f * v.y);
        *reinterpret_cast<__nv_bfloat162*>(row + 2 * c) = hp;
    }
    g_cnorm[k] = cn + SBIAS;
}

// fp64 exact squared distance (tier-2, rare)
__device__ double dist2_f64(const float* __restrict__ zp,
                            const float* __restrict__ cb, int idx) {
    const float* cp = cb + (size_t)idx * CC;
    double d = 0.0;
#pragma unroll
    for (int c = 0; c < CC; c++) {
        double df = (double)zp[(size_t)c * HWN] - (double)__ldg(cp + c);
        d = fma(df, df, d);
    }
    return d;
}

// ---------------------------------------------------------------------------
// Kernel 1: HMMA VQ, M=64 tiles — bf16 screen, packed branch-free top-4-of-256,
//           fp32 rescore + fp64 tie refinement, fused deterministic loss
// ---------------------------------------------------------------------------
extern __shared__ unsigned char dynsmem[];

__global__ __launch_bounds__(THREADS, 5)
void vq_kernel(const float* __restrict__ z,
               const float* __restrict__ cb,
               float* __restrict__ out,
               float* __restrict__ loss_out) {
    const int tid = threadIdx.x;
    const int w = tid >> 5;
    const int l = tid & 31;
    const uint32_t sb = smem_to_u32(dynsmem);

    __nv_bfloat16* Ahi = reinterpret_cast<__nv_bfloat16*>(dynsmem + OFF_BUF0);
    float* werr = reinterpret_cast<float*>(dynsmem + OFF_WERR);
    uint32_t* cand = reinterpret_cast<uint32_t*>(dynsmem + OFF_BUF0);  // post-loop

    // --- A tile: 64 queries -> bf16 hi (thread t: row t&63, half t>>6) ---
    {
        const int r = tid & 63;
        const int half = tid >> 6;
        const int qs = blockIdx.x * MTILE + r;
        const float* zs = z + (size_t)(qs >> 12) * CC * HWN + (qs & (HWN - 1));
#pragma unroll
        for (int c = half * 32; c < half * 32 + 32; c++)
            Ahi[r * PADW + c] = __float2bfloat16_rn(zs[(size_t)c * HWN]);
    }
    __syncthreads();

    // --- hoist A fragments: 4 k-slices x 4 regs (one m16 tile per warp) ---
    const int rowA = w * 16 + (l & 15);
    const int colA = ((l >> 4) & 1) * 8;
    uint32_t afr[16];
#pragma unroll
    for (int fi = 0; fi < 4; fi++)
        LDSM_X4(afr + fi * 4,
                sb + OFF_BUF0 + (uint32_t)(rowA * PADW + colA + fi * 16) * 2);
    __syncthreads();   // buf0 free for prefetch

    // --- prefetch chunks 0,1 via cp.async (double buffer) ---
    const uint32_t bufB[2]   = { sb + OFF_BUF0, sb + OFF_BUF1 };
    const uint32_t bufSCN[2] = { sb + OFF_SCN0, sb + OFF_SCN1 };
#pragma unroll
    for (int p = 0; p < 2; p++) {
        const char* src = reinterpret_cast<const char*>(g_cbimg) + (size_t)p * BBYTES;
#pragma unroll
        for (int i = 0; i < 9; i++)
            CP_ASYNC16(bufB[p] + (uint32_t)(tid + i * THREADS) * 16,
                       src + (size_t)(tid + i * THREADS) * 16);
        CP_ASYNC4(bufSCN[p] + (uint32_t)tid * 4,
                  reinterpret_cast<const char*>(g_cnorm) + (size_t)(p * NCHUNK + tid) * 4);
        CP_COMMIT();
    }

    // per-slot packed top-4 (slot = e>>1: 2 query rows per thread)
    // packed = (float_bits(score) & ~0xFF) | (iter*8 + nt*2 + e1)
    uint32_t pm[8];
#pragma unroll
    for (int i = 0; i < 8; i++) pm[i] = 0xFFFFFFFFu;

    const int rowB = ((l >> 4) & 1) * 8 + (l & 7);
    const int colB = ((l >> 3) & 1) * 8;

#pragma unroll 1
    for (int ch = 0; ch < NCH; ch++) {
        CP_WAIT1();
        __syncthreads();

        const uint32_t Bc = bufB[ch & 1];
        const float* scn = reinterpret_cast<const float*>(
            dynsmem + (((ch & 1) ? OFF_SCN1 : OFF_SCN0)));

#pragma unroll 1
        for (int nsub = 0; nsub < 4; nsub++) {
            float2 cnp[4];
#pragma unroll
            for (int nt = 0; nt < 4; nt++)
                cnp[nt] = *reinterpret_cast<const float2*>(
                    scn + nsub * 32 + nt * 8 + 2 * (l & 3));

            float d[16];
            const uint32_t bbase = Bc + (uint32_t)((nsub * 32 + rowB) * PADW + colB) * 2;

#pragma unroll
            for (int s = 0; s < 4; s++) {
                uint32_t bf[8];
                LDSM_X4(bf,     bbase + (uint32_t)(s * 16) * 2);
                LDSM_X4(bf + 4, bbase + (uint32_t)(16 * PADW + s * 16) * 2);
                const uint32_t* a0 = afr + s * 4;
                if (s == 0) {
#pragma unroll
                    for (int nt = 0; nt < 4; nt++)
                        MMA16816_INIT(d + nt * 4, a0, bf + nt * 2,
                                      cnp[nt].x, cnp[nt].y);
                } else {
#pragma unroll
                    for (int nt = 0; nt < 4; nt++)
                        MMA16816(d + nt * 4, a0, bf + nt * 2);
                }
            }

            // packed branch-free top-4 insert: 1 LOP3 + 7 IMNMX per score
            const uint32_t base8 = (uint32_t)((ch * 4 + nsub) * 8);
#pragma unroll
            for (int nt = 0; nt < 4; nt++)
#pragma unroll
                for (int e = 0; e < 4; e++) {
                    uint32_t x = (__float_as_uint(d[nt * 4 + e]) & 0xFFFFFF00u)
                               | (base8 + (uint32_t)(nt * 2 + (e & 1)));
                    uint32_t* p = pm + (e >> 1) * 4;
                    uint32_t t;
                    t = umn(p[0], x); x = umx(p[0], x); p[0] = t;
                    t = umn(p[1], x); x = umx(p[1], x); p[1] = t;
                    t = umn(p[2], x); x = umx(p[2], x); p[2] = t;
                    p[3] = umn(p[3], x);
                }
        }

        __syncthreads();
        if (ch + 2 < NCH) {
            const char* src = reinterpret_cast<const char*>(g_cbimg) + (size_t)(ch + 2) * BBYTES;
#pragma unroll
            for (int i = 0; i < 9; i++)
                CP_ASYNC16(bufB[ch & 1] + (uint32_t)(tid + i * THREADS) * 16,
                           src + (size_t)(tid + i * THREADS) * 16);
            CP_ASYNC4(bufSCN[ch & 1] + (uint32_t)tid * 4,
                      reinterpret_cast<const char*>(g_cnorm) + (size_t)((ch + 2) * NCHUNK + tid) * 4);
            CP_COMMIT();
        }
    }

    // --- merge packed candidates via smem (stride 17; reuses buf0) ---
    // query row qr gets 16 entries: 4 lane groups (l&3) x top-4
#pragma unroll
    for (int s = 0; s < 2; s++) {
        int qr = w * 16 + (l >> 2) + 8 * s;
#pragma unroll
        for (int e = 0; e < 4; e++)
            cand[qr * 17 + (l & 3) * 4 + e] = pm[s * 4 + e];
    }
    __syncthreads();

    // --- per-query (threads 0..63): window + fp32 rescore + fp64 tie ---
    float err = 0.f;
    if (tid < MTILE) {
        const int q = blockIdx.x * MTILE + tid;
        const int b = q >> 12;
        const float* zp = z + (size_t)b * CC * HWN + (q & (HWN - 1));

        uint32_t pmin = cand[tid * 17];
#pragma unroll
        for (int j = 1; j < 16; j++) pmin = umn(pmin, cand[tid * 17 + j]);
        const float smin = __uint_as_float(pmin & 0xFFFFFF00u);

        int wc[16]; int nw = 0;
#pragma unroll
        for (int j = 0; j < 16; j++) {
            uint32_t pj = cand[tid * 17 + j];
            float sc = __uint_as_float(pj & 0xFFFFFF00u);
            if (sc < smin + EPS_SCREEN) {
                uint32_t low = pj & 0xFFu;
                wc[nw++] = (int)(low >> 3) * 32 + (int)((low >> 1) & 3) * 8
                         + 2 * (j >> 2) + (int)(low & 1);
            }
        }

        int bidx;
        if (nw == 1) {
            bidx = wc[0];
        } else {
            float best = 3.4e38f, second = 3.4e38f;
            int   bi = 0x7fffffff;
#pragma unroll 1
            for (int j0 = 0; j0 < nw; j0 += 2) {
                int iA = wc[j0];
                int iB = wc[(j0 + 1 < nw) ? (j0 + 1) : j0];
                const float4* pA = reinterpret_cast<const float4*>(cb + (size_t)iA * CC);
                const float4* pB = reinterpret_cast<const float4*>(cb + (size_t)iB * CC);
                float dA0 = 0.f, dA1 = 0.f, dB0 = 0.f, dB1 = 0.f;
#pragma unroll
                for (int c = 0; c < CC / 4; c++) {
                    float4 a4 = __ldg(pA + c);
                    float4 b4 = __ldg(pB + c);
                    float z0 = zp[(size_t)(4 * c + 0) * HWN];
                    float z1 = zp[(size_t)(4 * c + 1) * HWN];
                    float z2 = zp[(size_t)(4 * c + 2) * HWN];
                    float z3 = zp[(size_t)(4 * c + 3) * HWN];
                    float tA0 = z0 - a4.x, tA1 = z1 - a4.y, tA2 = z2 - a4.z, tA3 = z3 - a4.w;
                    float tB0 = z0 - b4.x, tB1 = z1 - b4.y, tB2 = z2 - b4.z, tB3 = z3 - b4.w;
                    dA0 = fmaf(tA0, tA0, dA0); dA1 = fmaf(tA1, tA1, dA1);
                    dA0 = fmaf(tA2, tA2, dA0); dA1 = fmaf(tA3, tA3, dA1);
                    dB0 = fmaf(tB0, tB0, dB0); dB1 = fmaf(tB1, tB1, dB1);
                    dB0 = fmaf(tB2, tB2, dB0); dB1 = fmaf(tB3, tB3, dB1);
                }
                float dA = dA0 + dA1;
                float dB = dB0 + dB1;
                if (dA < best || (dA == best && iA < bi)) {
                    second = best; best = dA; bi = iA;
                } else {
                    second = fminf(second, dA);
                }
                if (j0 + 1 < nw) {
                    if (dB < best || (dB == best && iB < bi)) {
                        second = best; best = dB; bi = iB;
                    } else {
                        second = fminf(second, dB);
                    }
                }
            }

            if (second < best + EPS_TIE) {
                double bd = 1e300;
                int bi64 = 0x7fffffff;
#pragma unroll 1
                for (int j = 0; j < nw; j++) {
                    double dd = dist2_f64(zp, cb, wc[j]);
                    if (dd < bd || (dd == bd && wc[j] < bi64)) { bd = dd; bi64 = wc[j]; }
                }
                bi = bi64;
            }
            bidx = bi;
        }

        // write z_q + squared error
        const float4* cv4 = reinterpret_cast<const float4*>(cb + (size_t)bidx * CC);
        float* op = out + (size_t)b * CC * HWN + (q & (HWN - 1));
#pragma unroll
        for (int i = 0; i < CC / 4; i++) {
            float4 v = __ldg(cv4 + i);
            float z0 = zp[(size_t)(4 * i + 0) * HWN];
            float z1 = zp[(size_t)(4 * i + 1) * HWN];
            float z2 = zp[(size_t)(4 * i + 2) * HWN];
            float z3 = zp[(size_t)(4 * i + 3) * HWN];
            op[(size_t)(4 * i + 0) * HWN] = v.x;
            op[(size_t)(4 * i + 1) * HWN] = v.y;
            op[(size_t)(4 * i + 2) * HWN] = v.z;
            op[(size_t)(4 * i + 3) * HWN] = v.w;
            float d0 = v.x - z0, d1 = v.y - z1, d2 = v.z - z2, d3 = v.w - z3;
            err = fmaf(d0, d0, err);
            err = fmaf(d1, d1, err);
            err = fmaf(d2, d2, err);
            err = fmaf(d3, d3, err);
        }
    }

#pragma unroll
    for (int o = 16; o > 0; o >>= 1)
        err += __shfl_down_sync(0xFFFFFFFFu, err, o);
    if (l == 0) werr[w] = err;
    __syncthreads();

    // --- fused deterministic loss: last CTA reduces all partials ---
    __shared__ unsigned int s_last;
    if (tid == 0) {
        g_partials[blockIdx.x] = werr[0] + werr[1] + werr[2] + werr[3];
        __threadfence();
        unsigned int old = atomicAdd(&g_ctr, 1u);
        s_last = (old == NBLOCKS - 1) ? 1u : 0u;
    }
    __syncthreads();
    if (s_last) {
        __threadfence();  // acquire: all partials visible
        double* sd = reinterpret_cast<double*>(dynsmem);  // loop done; reuse smem
        double acc = 0.0;
#pragma unroll
        for (int i = 0; i < NBLOCKS / THREADS; i++)
            acc += (double)g_partials[tid * (NBLOCKS / THREADS) + i];
        sd[tid] = acc;
        __syncthreads();
#pragma unroll
        for (int st = THREADS / 2; st > 0; st >>= 1) {
            if (tid < st) sd[tid] += sd[tid + st];
            __syncthreads();
        }
        if (tid == 0) {
            if (loss_out)
                loss_out[0] = (float)(1.25 * sd[0] / (double)ZELEMS);
            g_ctr = 0;  // reset for next graph replay
        }
    }
}

// ---------------------------------------------------------------------------
extern "C" void kernel_launch(void* const* d_in, const int* in_sizes, int n_in,
                              void* d_out, int out_size) {
    const float* z  = (const float*)d_in[0];
    const float* cb = (const float*)d_in[1];
    float* out = (float*)d_out;
    float* loss_out = (out_size > ZELEMS) ? (out + ZELEMS) : nullptr;

    cudaFuncSetAttribute(vq_kernel, cudaFuncAttributeMaxDynamicSharedMemorySize,
                         SMEM_TOTAL);

    prep_kernel<<<8, 128>>>(cb);
    vq_kernel<<<NBLOCKS, THREADS, SMEM_TOTAL>>>(z, cb, out, loss_out);
}

// round 17
// speedup vs baseline: 1.3918x; 1.3710x over previous
#include <cuda_runtime.h>
#include <cuda_bf16.h>
#include <cstdint>

// Problem constants (z: [32,64,64,64] f32, codebook: [1024,64] f32)
#define BB      32
#define CC      64
#define HWN     4096
#define NQ      (BB * HWN)        // 131072 queries
#define KCODES  1024
#define MTILE   128               // queries per CTA
#define NCHUNK  128               // codes staged per smem chunk
#define NCH     (KCODES / NCHUNK) // 8
#define THREADS 128
#define NBLOCKS (NQ / MTILE)      // 1024
#define ZELEMS  (BB * CC * HWN)
#define EPS_SCREEN 0.75f          // screen window (2x bf16 err 0.25 + pack 0.008 + margin)
#define EPS_TIE    5e-3f          // fp32 diff-form tie gate (>>2e-5 error bound)
#define SBIAS      256.0f         // score bias: makes all screen scores positive normals
#define PADW    72                // row stride (bf16): 144B = 9*16B, ldmatrix conflict-free

#define BBYTES  (NCHUNK * PADW * 2)            // 18432 per chunk image
#define OFF_BUF0   0
#define OFF_BUF1   (BBYTES + 512)              // 18944
#define OFF_SCN0   BBYTES
#define OFF_SCN1   (OFF_BUF1 + BBYTES)
#define OFF_WERR   (OFF_BUF1 + BBYTES + 512)   // 37888
#define SMEM_TOTAL (OFF_WERR + 64)             // 37952

__device__ float g_cnorm[KCODES];              // ||c||^2 + SBIAS
__device__ float g_partials[NBLOCKS];
__device__ unsigned int g_ctr = 0;
// prepped codebook: bf16 of (-2c), rows padded to PADW
__device__ __align__(16) __nv_bfloat16 g_cbimg[KCODES * PADW];

// ---------------------------------------------------------------------------
__device__ __forceinline__ uint32_t smem_to_u32(const void* p) {
    uint32_t a;
    asm("{ .reg .u64 t; cvta.to.shared.u64 t, %1; cvt.u32.u64 %0, t; }"
        : "=r"(a) : "l"(p));
    return a;
}
__device__ __forceinline__ uint32_t umn(uint32_t a, uint32_t b) { return a < b ? a : b; }
__device__ __forceinline__ uint32_t umx(uint32_t a, uint32_t b) { return a > b ? a : b; }

#define LDSM_X4(r, addr) \
    asm volatile("ldmatrix.sync.aligned.m8n8.x4.shared.b16 {%0,%1,%2,%3}, [%4];" \
        : "=r"((r)[0]), "=r"((r)[1]), "=r"((r)[2]), "=r"((r)[3]) : "r"(addr))

// accumulate: d += a*b
#define MMA16816(d, a, b) \
    asm volatile("mma.sync.aligned.m16n8k16.row.col.f32.bf16.bf16.f32 " \
        "{%0,%1,%2,%3}, {%4,%5,%6,%7}, {%8,%9}, {%0,%1,%2,%3};" \
        : "+f"((d)[0]), "+f"((d)[1]), "+f"((d)[2]), "+f"((d)[3]) \
        : "r"((a)[0]), "r"((a)[1]), "r"((a)[2]), "r"((a)[3]), \
          "r"((b)[0]), "r"((b)[1]))

// init: d = a*b + {c0,c1,c0,c1}
#define MMA16816_INIT(d, a, b, c0, c1) \
    asm volatile("mma.sync.aligned.m16n8k16.row.col.f32.bf16.bf16.f32 " \
        "{%0,%1,%2,%3}, {%4,%5,%6,%7}, {%8,%9}, {%10,%11,%10,%11};" \
        : "=f"((d)[0]), "=f"((d)[1]), "=f"((d)[2]), "=f"((d)[3]) \
        : "r"((a)[0]), "r"((a)[1]), "r"((a)[2]), "r"((a)[3]), \
          "r"((b)[0]), "r"((b)[1]), "f"(c0), "f"(c1))

#define CP_ASYNC16(sm, gp) \
    asm volatile("cp.async.cg.shared.global [%0], [%1], 16;" :: "r"(sm), "l"(gp))
#define CP_ASYNC4(sm, gp) \
    asm volatile("cp.async.ca.shared.global [%0], [%1], 4;" :: "r"(sm), "l"(gp))
#define CP_COMMIT() asm volatile("cp.async.commit_group;" ::: "memory")
#define CP_WAIT1()  asm volatile("cp.async.wait_group 1;" ::: "memory")

// integer top-4 insertion network (alu pipe): 7 IMNMX
__device__ __forceinline__ void net_insert_u(uint32_t x, uint32_t* p) {
    uint32_t t;
    t = umn(p[0], x); x = umx(p[0], x); p[0] = t;
    t = umn(p[1], x); x = umx(p[1], x); p[1] = t;
    t = umn(p[2], x); x = umx(p[2], x); p[2] = t;
    p[3] = umn(p[3], x);
}

// float top-4 insertion network (fma pipe): 7 FMNMX — valid because all
// packed values are positive normal floats (uint order == float order)
__device__ __forceinline__ void net_insert_f(uint32_t xu, uint32_t* p) {
    float x = __uint_as_float(xu), t;
    float p0 = __uint_as_float(p[0]);
    float p1 = __uint_as_float(p[1]);
    float p2 = __uint_as_float(p[2]);
    float p3 = __uint_as_float(p[3]);
    t = fminf(p0, x); x = fmaxf(p0, x); p0 = t;
    t = fminf(p1, x); x = fmaxf(p1, x); p1 = t;
    t = fminf(p2, x); x = fmaxf(p2, x); p2 = t;
    p3 = fminf(p3, x);
    p[0] = __float_as_uint(p0);
    p[1] = __float_as_uint(p1);
    p[2] = __float_as_uint(p2);
    p[3] = __float_as_uint(p3);
}

// ---------------------------------------------------------------------------
// Kernel 0: prep — cn = ||c||^2 + SBIAS (fp32 exact), bf16 image of (-2c)
// ---------------------------------------------------------------------------
__global__ void prep_kernel(const float* __restrict__ cb) {
    int k = blockIdx.x * blockDim.x + threadIdx.x;
    if (k >= KCODES) return;
    const float2* r = reinterpret_cast<const float2*>(cb + (size_t)k * CC);
    __nv_bfloat16* row = g_cbimg + (size_t)k * PADW;
    float cn = 0.f;
#pragma unroll
    for (int c = 0; c < CC / 2; c++) {
        float2 v = __ldg(r + c);
        cn = fmaf(v.x, v.x, cn);
        cn = fmaf(v.y, v.y, cn);
        __nv_bfloat162 hp;
        hp.x = __float2bfloat16_rn(-2.f * v.x);
        hp.y = __float2bfloat16_rn(-2.f * v.y);
        *reinterpret_cast<__nv_bfloat162*>(row + 2 * c) = hp;
    }
    g_cnorm[k] = cn + SBIAS;
}

// fp64 exact squared distance (tier-2, rare)
__device__ double dist2_f64(const float* __restrict__ zp,
                            const float* __restrict__ cb, int idx) {
    const float* cp = cb + (size_t)idx * CC;
    double d = 0.0;
#pragma unroll
    for (int c = 0; c < CC; c++) {
        double df = (double)zp[(size_t)c * HWN] - (double)__ldg(cp + c);
        d = fma(df, df, d);
    }
    return d;
}

// ---------------------------------------------------------------------------
// Kernel 1: HMMA VQ — bf16 screen, packed branch-free top-4-of-256 with
//           FMA/ALU pipe-split networks, fp32 rescore + fp64 tie refinement,
//           fused deterministic loss
// ---------------------------------------------------------------------------
extern __shared__ unsigned char dynsmem[];

__global__ __launch_bounds__(THREADS, 4)
void vq_kernel(const float* __restrict__ z,
               const float* __restrict__ cb,
               float* __restrict__ out,
               float* __restrict__ loss_out) {
    const int tid = threadIdx.x;
    const int w = tid >> 5;
    const int l = tid & 31;
    const uint32_t sb = smem_to_u32(dynsmem);

    __nv_bfloat16* Ahi = reinterpret_cast<__nv_bfloat16*>(dynsmem + OFF_BUF0);
    float* werr = reinterpret_cast<float*>(dynsmem + OFF_WERR);
    uint32_t* cand = reinterpret_cast<uint32_t*>(dynsmem + OFF_BUF0);  // post-loop

    const int q = blockIdx.x * MTILE + tid;
    const int b = q >> 12;
    const float* zp = z + (size_t)b * CC * HWN + (q & (HWN - 1));

    // --- A tile: z query -> bf16 hi, staged transiently in buf0.B ---
#pragma unroll
    for (int c = 0; c < CC; c++)
        Ahi[tid * PADW + c] = __float2bfloat16_rn(zp[(size_t)c * HWN]);
    __syncthreads();

    // --- hoist A fragments: 4 k-slices x (a0[4], a1[4]) = 32 regs ---
    const int rowA = w * 32 + (l & 15);
    const int colA = ((l >> 4) & 1) * 8;
    uint32_t afr[32];
#pragma unroll
    for (int fi = 0; fi < 4; fi++) {
        LDSM_X4(afr + fi * 8,
                sb + OFF_BUF0 + (uint32_t)((rowA)      * PADW + colA + fi * 16) * 2);
        LDSM_X4(afr + fi * 8 + 4,
                sb + OFF_BUF0 + (uint32_t)((rowA + 16) * PADW + colA + fi * 16) * 2);
    }
    __syncthreads();   // buf0 free for prefetch

    // --- prefetch chunks 0,1 via cp.async (double buffer) ---
    const uint32_t bufB[2]   = { sb + OFF_BUF0, sb + OFF_BUF1 };
    const uint32_t bufSCN[2] = { sb + OFF_SCN0, sb + OFF_SCN1 };
#pragma unroll
    for (int p = 0; p < 2; p++) {
        const char* src = reinterpret_cast<const char*>(g_cbimg) + (size_t)p * BBYTES;
#pragma unroll
        for (int i = 0; i < 9; i++)
            CP_ASYNC16(bufB[p] + (uint32_t)(tid + i * THREADS) * 16,
                       src + (size_t)(tid + i * THREADS) * 16);
        CP_ASYNC4(bufSCN[p] + (uint32_t)tid * 4,
                  reinterpret_cast<const char*>(g_cnorm) + (size_t)(p * NCHUNK + tid) * 4);
        CP_COMMIT();
    }

    // per-slot packed top-4 (sorted ascending). slot = mt*2 + (e>>1).
    // packed = (float_bits(score) & ~0xFF) | (iter*8 + nt*2 + e1)
    // init = FLT_MAX bits (valid positive float; never NaN for FMNMX slots)
    uint32_t pm[16];
#pragma unroll
    for (int i = 0; i < 16; i++) pm[i] = 0x7F7FFFFFu;

    const int rowB = ((l >> 4) & 1) * 8 + (l & 7);
    const int colB = ((l >> 3) & 1) * 8;

#pragma unroll 1
    for (int ch = 0; ch < NCH; ch++) {
        CP_WAIT1();
        __syncthreads();

        const uint32_t Bc = bufB[ch & 1];
        const float* scn = reinterpret_cast<const float*>(
            dynsmem + (((ch & 1) ? OFF_SCN1 : OFF_SCN0)));

#pragma unroll 1
        for (int nsub = 0; nsub < 4; nsub++) {
            float2 cnp[4];
#pragma unroll
            for (int nt = 0; nt < 4; nt++)
                cnp[nt] = *reinterpret_cast<const float2*>(
                    scn + nsub * 32 + nt * 8 + 2 * (l & 3));

            float d[32];
            const uint32_t bbase = Bc + (uint32_t)((nsub * 32 + rowB) * PADW + colB) * 2;

#pragma unroll
            for (int s = 0; s < 4; s++) {
                uint32_t bf[8];
                LDSM_X4(bf,     bbase + (uint32_t)(s * 16) * 2);
                LDSM_X4(bf + 4, bbase + (uint32_t)(16 * PADW + s * 16) * 2);
                const uint32_t* a0 = afr + s * 8;
                if (s == 0) {
#pragma unroll
                    for (int nt = 0; nt < 4; nt++) {
                        MMA16816_INIT(d + (0 * 4 + nt) * 4, a0,     bf + nt * 2,
                                      cnp[nt].x, cnp[nt].y);
                        MMA16816_INIT(d + (1 * 4 + nt) * 4, a0 + 4, bf + nt * 2,
                                      cnp[nt].x, cnp[nt].y);
                    }
                } else {
#pragma unroll
                    for (int nt = 0; nt < 4; nt++) {
                        MMA16816(d + (0 * 4 + nt) * 4, a0,     bf + nt * 2);
                        MMA16816(d + (1 * 4 + nt) * 4, a0 + 4, bf + nt * 2);
                    }
                }
            }

            // packed branch-free top-4 insert, pipe-split:
            //   mt=0 slots -> float FMNMX network (fma pipe)
            //   mt=1 slots -> integer IMNMX network (alu pipe)
            const uint32_t base8 = (uint32_t)((ch * 4 + nsub) * 8);
#pragma unroll
            for (int nt = 0; nt < 4; nt++)
#pragma unroll
                for (int e = 0; e < 4; e++) {
                    uint32_t x0 = (__float_as_uint(d[(0 * 4 + nt) * 4 + e])
                                   & 0xFFFFFF00u)
                                | (base8 + (uint32_t)(nt * 2 + (e & 1)));
                    net_insert_f(x0, pm + (0 * 2 + (e >> 1)) * 4);
                    uint32_t x1 = (__float_as_uint(d[(1 * 4 + nt) * 4 + e])
                                   & 0xFFFFFF00u)
                                | (base8 + (uint32_t)(nt * 2 + (e & 1)));
                    net_insert_u(x1, pm + (1 * 2 + (e >> 1)) * 4);
                }
        }

        __syncthreads();
        if (ch + 2 < NCH) {
            const char* src = reinterpret_cast<const char*>(g_cbimg) + (size_t)(ch + 2) * BBYTES;
#pragma unroll
            for (int i = 0; i < 9; i++)
                CP_ASYNC16(bufB[ch & 1] + (uint32_t)(tid + i * THREADS) * 16,
                           src + (size_t)(tid + i * THREADS) * 16);
            CP_ASYNC4(bufSCN[ch & 1] + (uint32_t)tid * 4,
                      reinterpret_cast<const char*>(g_cnorm) + (size_t)((ch + 2) * NCHUNK + tid) * 4);
            CP_COMMIT();
        }
    }

    // --- merge packed candidates via smem (stride 17; reuses buf0) ---
    // entry j of query: j>>2 = producing lane group (l&3), j&3 = rank
#pragma unroll
    for (int s = 0; s < 4; s++) {
        int mt = s >> 1, half = s & 1;
        int ql = w * 32 + mt * 16 + half * 8 + (l >> 2);
#pragma unroll
        for (int e = 0; e < 4; e++)
            cand[ql * 17 + (l & 3) * 4 + e] = pm[s * 4 + e];
    }
    __syncthreads();

    // --- per-query (thread = query): window + fp32 rescore + fp64 tie ---
    uint32_t cp16[16];
#pragma unroll
    for (int j = 0; j < 16; j++) cp16[j] = cand[tid * 17 + j];

    uint32_t pmin = cp16[0];
#pragma unroll
    for (int j = 1; j < 16; j++) pmin = umn(pmin, cp16[j]);
    const float smin = __uint_as_float(pmin & 0xFFFFFF00u);

    // decode window candidates (code idx from packed low byte + lane group)
    int wc[16]; int nw = 0;
#pragma unroll
    for (int j = 0; j < 16; j++) {
        float sc = __uint_as_float(cp16[j] & 0xFFFFFF00u);
        if (sc < smin + EPS_SCREEN) {
            uint32_t low = cp16[j] & 0xFFu;
            int iter = (int)(low >> 3);
            int nt   = (int)((low >> 1) & 3);
            int e1   = (int)(low & 1);
            wc[nw++] = iter * 32 + nt * 8 + 2 * (j >> 2) + e1;
        }
    }

    int bidx;
    if (nw == 1) {
        bidx = wc[0];
    } else {
        // tier 1: fp32 diff-form, two candidates per pass
        float dv[16];
        float best = 3.4e38f;
        int   bi = 0x7fffffff;
#pragma unroll 1
        for (int j0 = 0; j0 < nw; j0 += 2) {
            int iA = wc[j0];
            int iB = wc[(j0 + 1 < nw) ? (j0 + 1) : j0];
            const float4* pA = reinterpret_cast<const float4*>(cb + (size_t)iA * CC);
            const float4* pB = reinterpret_cast<const float4*>(cb + (size_t)iB * CC);
            float dA0 = 0.f, dA1 = 0.f, dB0 = 0.f, dB1 = 0.f;
#pragma unroll
            for (int c = 0; c < CC / 4; c++) {
                float4 a4 = __ldg(pA + c);
                float4 b4 = __ldg(pB + c);
                float z0 = zp[(size_t)(4 * c + 0) * HWN];
                float z1 = zp[(size_t)(4 * c + 1) * HWN];
                float z2 = zp[(size_t)(4 * c + 2) * HWN];
                float z3 = zp[(size_t)(4 * c + 3) * HWN];
                float tA0 = z0 - a4.x, tA1 = z1 - a4.y, tA2 = z2 - a4.z, tA3 = z3 - a4.w;
                float tB0 = z0 - b4.x, tB1 = z1 - b4.y, tB2 = z2 - b4.z, tB3 = z3 - b4.w;
                dA0 = fmaf(tA0, tA0, dA0); dA1 = fmaf(tA1, tA1, dA1);
                dA0 = fmaf(tA2, tA2, dA0); dA1 = fmaf(tA3, tA3, dA1);
                dB0 = fmaf(tB0, tB0, dB0); dB1 = fmaf(tB1, tB1, dB1);
                dB0 = fmaf(tB2, tB2, dB0); dB1 = fmaf(tB3, tB3, dB1);
            }
            float dA = dA0 + dA1;
            float dB = dB0 + dB1;
            dv[j0] = dA;
            if (dA < best || (dA == best && iA < bi)) { best = dA; bi = iA; }
            if (j0 + 1 < nw) {
                dv[j0 + 1] = dB;
                if (dB < best || (dB == best && iB < bi)) { best = dB; bi = iB; }
            }
        }

        // tier 2: fp64 only on fp32 near-ties (rare)
        int ntie = 0;
#pragma unroll 1
        for (int j = 0; j < nw; j++)
            if (dv[j] < best + EPS_TIE) ntie++;
        if (ntie > 1) {
            double bd = 1e300;
            int bi64 = 0x7fffffff;
#pragma unroll 1
            for (int j = 0; j < nw; j++) {
                if (dv[j] < best + EPS_TIE) {
                    double dd = dist2_f64(zp, cb, wc[j]);
                    if (dd < bd || (dd == bd && wc[j] < bi64)) { bd = dd; bi64 = wc[j]; }
                }
            }
            bi = bi64;
        }
        bidx = bi;
    }

    // --- write z_q + squared-error partial (coalesced; cb row as float4) ---
    float err = 0.f;
    {
        const float4* cv4 = reinterpret_cast<const float4*>(cb + (size_t)bidx * CC);
        float* op = out + (size_t)b * CC * HWN + (q & (HWN - 1));
#pragma unroll
        for (int i = 0; i < CC / 4; i++) {
            float4 v = __ldg(cv4 + i);
            float z0 = zp[(size_t)(4 * i + 0) * HWN];
            float z1 = zp[(size_t)(4 * i + 1) * HWN];
            float z2 = zp[(size_t)(4 * i + 2) * HWN];
            float z3 = zp[(size_t)(4 * i + 3) * HWN];
            op[(size_t)(4 * i + 0) * HWN] = v.x;
            op[(size_t)(4 * i + 1) * HWN] = v.y;
            op[(size_t)(4 * i + 2) * HWN] = v.z;
            op[(size_t)(4 * i + 3) * HWN] = v.w;
            float d0 = v.x - z0, d1 = v.y - z1, d2 = v.z - z2, d3 = v.w - z3;
            err = fmaf(d0, d0, err);
            err = fmaf(d1, d1, err);
            err = fmaf(d2, d2, err);
            err = fmaf(d3, d3, err);
        }
    }
#pragma unroll
    for (int o = 16; o > 0; o >>= 1)
        err += __shfl_down_sync(0xFFFFFFFFu, err, o);
    if (l == 0) werr[w] = err;
    __syncthreads();

    // --- fused deterministic loss: last CTA reduces all partials ---
    __shared__ unsigned int s_last;
    if (tid == 0) {
        g_partials[blockIdx.x] = werr[0] + werr[1] + werr[2] + werr[3];
        __threadfence();
        unsigned int old = atomicAdd(&g_ctr, 1u);
        s_last = (old == NBLOCKS - 1) ? 1u : 0u;
    }
    __syncthreads();
    if (s_last) {
        __threadfence();  // acquire: all partials visible
        double* sd = reinterpret_cast<double*>(dynsmem);  // loop done; reuse smem
        double acc = 0.0;
#pragma unroll
        for (int i = 0; i < NBLOCKS / THREADS; i++)
            acc += (double)g_partials[tid * (NBLOCKS / THREADS) + i];
        sd[tid] = acc;
        __syncthreads();
#pragma unroll
        for (int st = THREADS / 2; st > 0; st >>= 1) {
            if (tid < st) sd[tid] += sd[tid + st];
            __syncthreads();
        }
        if (tid == 0) {
            if (loss_out)
                loss_out[0] = (float)(1.25 * sd[0] / (double)ZELEMS);
            g_ctr = 0;  // reset for next graph replay
        }
    }
}

// ---------------------------------------------------------------------------
extern "C" void kernel_launch(void* const* d_in, const int* in_sizes, int n_in,
                              void* d_out, int out_size) {
    const float* z  = (const float*)d_in[0];
    const float* cb = (const float*)d_in[1];
    float* out = (float*)d_out;
    float* loss_out = (out_size > ZELEMS) ? (out + ZELEMS) : nullptr;

    cudaFuncSetAttribute(vq_kernel, cudaFuncAttributeMaxDynamicSharedMemorySize,
                         SMEM_TOTAL);

    prep_kernel<<<8, 128>>>(cb);
    vq_kernel<<<NBLOCKS, THREADS, SMEM_TOTAL>>>(z, cb, out, loss_out);
}